// round 8
// baseline (speedup 1.0000x reference)
#include <cuda_runtime.h>
#include <cstdint>
#include <cstddef>

#define FULLMASK 0xffffffffu

// ---------------- problem constants ----------------
constexpr int Bc  = 2;
constexpr int Hc  = 8;
constexpr int Sc  = 2048;
constexpr int Dc  = 128;
constexpr int Mc  = 32768;
constexpr int NQ  = Bc * Sc;        // 4096 queries per head
// ---------------- tiling ----------------
constexpr int TQ  = 128;            // queries per block
constexpr int TK  = 128;            // keys per tile
constexpr int DCH = 16;             // dims staged per pipeline stage
constexpr int KSTRIDE = 20;         // padded floats per key row (80B, 16B aligned)
constexpr int NCHUNK = Dc / DCH;    // 8 stages per key tile
constexpr int NTILES = Mc / TK;     // 256
constexpr int NST = NTILES * NCHUNK;// 2048 pipeline stages
constexpr int KBUF = TK * KSTRIDE;  // 2560 floats per K buffer

// smem float offsets
constexpr int OFF_QS = 0;                       // [Dc][TQ]        16384
constexpr int OFF_KS = OFF_QS + Dc * TQ;        // [3][TK][KSTRIDE] 7680
constexpr int OFF_LS = OFF_KS + 3 * KBUF;       // [TQ][16]         2048
constexpr int OFF_LI = OFF_LS + TQ * 16;        // [TQ][16]         2048
constexpr int OFF_TH = OFF_LI + TQ * 16;        // [TQ]              128
constexpr int SMEM_FLOATS = OFF_TH + TQ;        // 28288 floats = 113152 B

// ---------------- packed fp32x2 helpers (Blackwell full-rate fp32) ----------
static __device__ __forceinline__ void fma2(unsigned long long& acc,
                                            unsigned long long a,
                                            unsigned long long b) {
    asm("fma.rn.f32x2 %0, %1, %2, %0;" : "+l"(acc) : "l"(a), "l"(b));
}
static __device__ __forceinline__ unsigned long long pack2(float a) {
    unsigned long long r;
    asm("mov.b64 %0, {%1, %1};" : "=l"(r) : "f"(a));
    return r;
}
static __device__ __forceinline__ float2 unpack2(unsigned long long v) {
    float2 r;
    asm("mov.b64 {%0, %1}, %2;" : "=f"(r.x), "=f"(r.y) : "l"(v));
    return r;
}
static __device__ __forceinline__ void cpasync16(uint32_t dst, const void* src) {
    asm volatile("cp.async.cg.shared.global [%0], [%1], 16;" :: "r"(dst), "l"(src));
}
static __device__ __forceinline__ void cp_commit() {
    asm volatile("cp.async.commit_group;" ::: "memory");
}
static __device__ __forceinline__ void cp_wait1() {
    asm volatile("cp.async.wait_group 1;" ::: "memory");
}

__global__ __launch_bounds__(256, 2)
void praxis_fused_kernel(const float* __restrict__ Q,      // [B,H,S,D]
                         const float* __restrict__ Outp,   // [B,H,S,D]
                         const float* __restrict__ Gate,   // [H]
                         const float* __restrict__ Kmem,   // [H,M,D] (pre-normalized)
                         const float* __restrict__ Vmem,   // [H,M,D]
                         float* __restrict__ Out)          // [B,H,S,D]
{
    extern __shared__ float smem[];
    float* Qs = smem + OFF_QS;
    float* Ks = smem + OFF_KS;
    float* Ls = smem + OFF_LS;
    int*   Li = reinterpret_cast<int*>(smem + OFF_LI);
    float* Th = smem + OFF_TH;

    const int tid  = threadIdx.x;
    const int tx   = tid & 15;         // key group (16); keys tx + 16j
    const int ty   = tid >> 4;         // query group (16): queries 8ty..8ty+7
    const int lane = tid & 31;
    const int h    = blockIdx.y;
    const int q0   = blockIdx.x * TQ;

    const float* KH = Kmem + (size_t)h * Mc * Dc;

    // ---------------- init top-k lists + thresholds ----------------
    #pragma unroll
    for (int i = tid; i < TQ * 16; i += 256) { Ls[i] = -1e30f; Li[i] = 0x7fffffff; }
    if (tid < TQ) Th[tid] = -1e30f;

    // ---- load + l2-normalize Q tile into Qs[d][q] --------------------------
    // Numerically VERBATIM from the R2/R6 kernels (rel_err ~1e-7): 4 lanes per
    // row, identical float4 sum expression, reduced xor1+xor2. Do not touch.
    #pragma unroll
    for (int half = 0; half < 2; ++half) {
        const int q    = tid >> 2;          // 0..63
        const int part = tid & 3;           // quarter of the 128-dim vector
        const int qrow = half * 64 + q;
        const int qg   = q0 + qrow;
        const int bq   = qg >> 11;
        const int sq   = qg & 2047;
        const float* qp = Q + ((((size_t)bq * Hc + h) * Sc + sq) * Dc) + part * 32;
        float4 v[8];
        float ss = 0.f;
        #pragma unroll
        for (int r = 0; r < 8; ++r) {
            v[r] = reinterpret_cast<const float4*>(qp)[r];
            ss += v[r].x * v[r].x + v[r].y * v[r].y + v[r].z * v[r].z + v[r].w * v[r].w;
        }
        ss += __shfl_xor_sync(FULLMASK, ss, 1);
        ss += __shfl_xor_sync(FULLMASK, ss, 2);
        const float inv = 1.0f / fmaxf(sqrtf(ss), 1e-12f);
        #pragma unroll
        for (int r = 0; r < 8; ++r) {
            const int d = part * 32 + r * 4;
            Qs[(d + 0) * TQ + qrow] = v[r].x * inv;
            Qs[(d + 1) * TQ + qrow] = v[r].y * inv;
            Qs[(d + 2) * TQ + qrow] = v[r].z * inv;
            Qs[(d + 3) * TQ + qrow] = v[r].w * inv;
        }
    }

    // ---------------- cp.async staging setup ----------------
    const uint32_t ks_u32 = (uint32_t)__cvta_generic_to_shared(Ks);
    const int r0  = tid >> 2;           // key row 0..63 (and r0+64)
    const int seg = tid & 3;            // 16B segment of the 64B chunk row

    // stage st covers tile st>>3, dims (st&7)*16 .. +15. Each thread copies
    // 2x16B: rows r0 and r0+64, segment seg.
    #define ISSUE_STAGE(st, buf)                                                 \
    {   const int _tile = (st) >> 3, _c = (st) & 7;                              \
        const float* _s = KH + ((size_t)(_tile * TK + r0)) * Dc + _c * DCH + seg * 4; \
        const uint32_t _d = ks_u32 + (uint32_t)((buf) * KBUF + r0 * KSTRIDE + seg * 4) * 4u; \
        cpasync16(_d, _s);                                                       \
        cpasync16(_d + (uint32_t)(64 * KSTRIDE * 4), _s + (size_t)64 * Dc);      \
        cp_commit();                                                             \
    }

    // prologue: stages 0,1 into buffers 0,1
    ISSUE_STAGE(0, 0)
    ISSUE_STAGE(1, 1)

    unsigned long long acc[4][8];       // [q-pair][key]; lanes = (q even, q odd)
    #pragma unroll
    for (int p = 0; p < 4; ++p)
        #pragma unroll
        for (int j = 0; j < 8; ++j) acc[p][j] = 0ULL;

    const unsigned hm = (lane < 16) ? 0x0000FFFFu : 0xFFFF0000u;
    const float* qbase = Qs + 8 * ty;

    int cbuf = 0, ibuf = 2;

    // ---------------- main pipeline over 2048 stages ----------------
    for (int st = 0; st < NST; ++st) {
        cp_wait1();                 // stage st complete (<=1 group pending)
        __syncthreads();            // cross-thread visibility + buffer reuse

        // -- compute stage st: dims (st&7)*16 .. +15, all 128 keys of tile --
        {
            const float* ksb = Ks + cbuf * KBUF;
            const int c = st & 7;
            #pragma unroll
            for (int g = 0; g < 4; ++g) {
                const int d0 = c * DCH + g * 4;
                ulonglong2 u01[4], u23[4];
                #pragma unroll
                for (int e = 0; e < 4; ++e) {
                    const float* qp = qbase + (d0 + e) * TQ;
                    u01[e] = *reinterpret_cast<const ulonglong2*>(qp);      // pairs q0q1,q2q3
                    u23[e] = *reinterpret_cast<const ulonglong2*>(qp + 4);  // pairs q4q5,q6q7
                }
                #pragma unroll
                for (int jb = 0; jb < 2; ++jb) {
                    float4 kv[4];
                    #pragma unroll
                    for (int j = 0; j < 4; ++j)
                        kv[j] = *reinterpret_cast<const float4*>(
                            ksb + (tx + 16 * (jb * 4 + j)) * KSTRIDE + g * 4);
                    #pragma unroll
                    for (int j = 0; j < 4; ++j) {
                        const int jj = jb * 4 + j;
                        #define STEP(comp, e)                                    \
                        {   unsigned long long aa = pack2(kv[j].comp);           \
                            fma2(acc[0][jj], aa, u01[e].x);                      \
                            fma2(acc[1][jj], aa, u01[e].y);                      \
                            fma2(acc[2][jj], aa, u23[e].x);                      \
                            fma2(acc[3][jj], aa, u23[e].y); }
                        STEP(x, 0) STEP(y, 1) STEP(z, 2) STEP(w, 3)
                        #undef STEP
                    }
                }
            }
        }

        // -- issue stage st+2 into ibuf (buffer freed: computed at st-1) --
        if (st + 2 < NST) { ISSUE_STAGE(st + 2, ibuf) }
        else              { cp_commit(); }   // keep group-count invariant

        cbuf = (cbuf == 2) ? 0 : cbuf + 1;
        ibuf = (ibuf == 2) ? 0 : ibuf + 1;

        // -- end of tile: top-16 update (tie rule = (score desc, index asc)) --
        if ((st & 7) == 7) {
            const int kt = st >> 3;
            const int kbase = kt * TK;
            #pragma unroll
            for (int i = 0; i < 8; ++i) {
                const int p = i >> 1;
                float sims[8];
                #pragma unroll
                for (int j = 0; j < 8; ++j) {
                    const float2 u = unpack2(acc[p][j]);
                    sims[j] = (i & 1) ? u.y : u.x;
                }
                const int row = ty * 8 + i;
                float throw_ = Th[row];          // broadcast LDS per half-warp

                float mx = sims[0];
                #pragma unroll
                for (int jj = 1; jj < 8; ++jj) mx = fmaxf(mx, sims[jj]);
                const unsigned bal = __ballot_sync(FULLMASK, mx >= throw_);
                if (bal) {
                    #pragma unroll
                    for (int jj = 0; jj < 8; ++jj) {
                        const float s = sims[jj];
                        const int kidx = kbase + tx + 16 * jj;
                        bool pending = s >= throw_;
                        unsigned ball;
                        while ((ball = __ballot_sync(FULLMASK, pending)) != 0) {
                            const unsigned bh = ball & hm;
                            const int src = bh ? (__ffs(bh) - 1) : lane;
                            float newthr = throw_;
                            if (bh && lane == src) {
                                float* lrow = Ls + row * 16;
                                int*   irow = Li + row * 16;
                                float mn = lrow[0]; int mj = 0; int mi = irow[0];
                                #pragma unroll
                                for (int j = 1; j < 16; ++j) {
                                    const float v = lrow[j];
                                    const int  vi = irow[j];
                                    if (v < mn || (v == mn && vi > mi)) {
                                        mn = v; mj = j; mi = vi;
                                    }
                                }
                                if (s > mn || (s == mn && kidx < mi)) {
                                    lrow[mj] = s; irow[mj] = kidx;
                                }
                                float t = lrow[0];
                                #pragma unroll
                                for (int j = 1; j < 16; ++j) t = fminf(t, lrow[j]);
                                newthr = t;
                            }
                            __syncwarp(FULLMASK);
                            const float bc = __shfl_sync(FULLMASK, newthr, src);
                            throw_ = bc;                    // own-half value when bh, else unchanged
                            if (bh) {
                                if (lane == src) pending = false;
                                pending = pending && (s >= throw_);
                            }
                        }
                    }
                    if ((lane & 15) == 0) Th[row] = throw_;
                }
            }
            #pragma unroll
            for (int p = 0; p < 4; ++p)
                #pragma unroll
                for (int j = 0; j < 8; ++j) acc[p][j] = 0ULL;
        }
    }
    #undef ISSUE_STAGE

    // ---------------- epilogue: gather V, weighted sum, gate blend ----------
    __syncthreads();
    const float gv = Gate[h];
    const float g  = 1.0f / (1.0f + expf(-gv));
    const float og = 1.0f - g;
    const float* VH = Vmem + (size_t)h * Mc * Dc;

    const int r    = tid >> 1;          // row within tile (0..127)
    const int part = tid & 1;           // which 64-dim half

    float4 a[16];
    #pragma unroll
    for (int m = 0; m < 16; ++m) a[m] = make_float4(0.f, 0.f, 0.f, 0.f);

    #pragma unroll 1
    for (int j = 0; j < 16; ++j) {
        const float sj = Ls[r * 16 + j];
        const int   vj = Li[r * 16 + j];
        const float4* vp = reinterpret_cast<const float4*>(VH + (size_t)vj * Dc + part * 64);
        #pragma unroll
        for (int m = 0; m < 16; ++m) {
            const float4 v = vp[m];
            a[m].x += sj * v.x; a[m].y += sj * v.y;
            a[m].z += sj * v.z; a[m].w += sj * v.w;
        }
    }

    {
        const int qg = q0 + r;
        const int bq = qg >> 11;
        const int sq = qg & 2047;
        const size_t off = (((size_t)bq * Hc + h) * Sc + sq) * Dc + part * 64;
        #pragma unroll
        for (int m = 0; m < 16; ++m) {
            const float4 o = *reinterpret_cast<const float4*>(Outp + off + 4 * m);
            float4 rr;
            rr.x = g * a[m].x + og * o.x;
            rr.y = g * a[m].y + og * o.y;
            rr.z = g * a[m].z + og * o.z;
            rr.w = g * a[m].w + og * o.w;
            *reinterpret_cast<float4*>(Out + off + 4 * m) = rr;
        }
    }
}

extern "C" void kernel_launch(void* const* d_in, const int* in_sizes, int n_in,
                              void* d_out, int out_size) {
    // metadata order: inputs(0), query(1), key(2), value(3), outputs(4),
    //                 gate(5), key_memories(6), value_memories(7)
    const float* query   = (const float*)d_in[1];
    const float* outputs = (const float*)d_in[4];
    const float* gate    = (const float*)d_in[5];
    const float* kmem    = (const float*)d_in[6];
    const float* vmem    = (const float*)d_in[7];
    float* out = (float*)d_out;

    const int smem_bytes = SMEM_FLOATS * (int)sizeof(float);   // 113152 B
    cudaFuncSetAttribute(praxis_fused_kernel,
                         cudaFuncAttributeMaxDynamicSharedMemorySize, smem_bytes);

    dim3 grid(NQ / TQ, Hc);   // 32 x 8 = 256 blocks -> single wave at occupancy 2
    praxis_fused_kernel<<<grid, 256, smem_bytes>>>(query, outputs, gate, kmem, vmem, out);
}

// round 11
// speedup vs baseline: 3.2135x; 3.2135x over previous
#include <cuda_runtime.h>
#include <cuda_bf16.h>
#include <cstdint>
#include <cstddef>

#define FULLMASK 0xffffffffu

constexpr int Bc=2, Hc=8, Sc=2048, Dc=128, Mc=32768;
constexpr int NQ = Bc*Sc;          // 4096 queries per head
constexpr int TQ = 128;            // queries per CTA
constexpr int TILEK = 64;          // keys per staged tile
constexpr int KSTRB = 272;         // padded smem bytes per key row (136 bf16)
constexpr int TBYTES = TILEK*KSTRB;// 17408 per buffer
constexpr int NT = Mc/TILEK;       // 512 tiles

// smem layout (byte offsets)
constexpr int SM_KB  = 0;              // 3 x 17408 = 52224 (overlays QS region)
constexpr int SM_CI  = 65536;          // u16 cand idx [128][64] = 16384
constexpr int SM_CS  = 65536+16384;    // f32 cand scores [128][64] = 32768
constexpr int SM_TOTAL = SM_CS+32768;  // 114688 B -> 2 CTAs/SM (229376 <= 232448)
// epilogue overlays (QS region dead): final lists
constexpr int SM_FS = 0;               // f32 [128][16]
constexpr int SM_FI = 8192;            // i32 [128][16]

__device__ __nv_bfloat16 g_kbf[(size_t)Hc*Mc*Dc];   // 64 MB bf16 keys

static __device__ __forceinline__ void cpasync16(uint32_t dst, const void* src) {
    asm volatile("cp.async.cg.shared.global [%0], [%1], 16;" :: "r"(dst), "l"(src));
}
#define CP_COMMIT() asm volatile("cp.async.commit_group;" ::: "memory")
#define CP_WAIT1()  asm volatile("cp.async.wait_group 1;" ::: "memory")
#define CP_WAIT0()  asm volatile("cp.async.wait_group 0;" ::: "memory")

static __device__ __forceinline__ uint32_t packbf(float lo, float hi) {
    __nv_bfloat162 p = __floats2bfloat162_rn(lo, hi);
    return *reinterpret_cast<uint32_t*>(&p);
}
static __device__ __forceinline__ void mma16816(float& c0, float& c1, float& c2, float& c3,
                                                uint32_t a0, uint32_t a1, uint32_t a2, uint32_t a3,
                                                uint32_t b0, uint32_t b1) {
    asm volatile("mma.sync.aligned.m16n8k16.row.col.f32.bf16.bf16.f32 "
                 "{%0,%1,%2,%3}, {%4,%5,%6,%7}, {%8,%9}, {%0,%1,%2,%3};"
                 : "+f"(c0), "+f"(c1), "+f"(c2), "+f"(c3)
                 : "r"(a0), "r"(a1), "r"(a2), "r"(a3), "r"(b0), "r"(b1));
}

// replace min entry of a 16-slot register list (scores fp32, idx packed 2xu16)
#define INSERT(sL, pL, thrL, sv, kv)                                             \
{   float _mn = sL[0]; int _mj = 0;                                              \
    _Pragma("unroll")                                                            \
    for (int _j = 1; _j < 16; ++_j) if (sL[_j] < _mn) { _mn = sL[_j]; _mj = _j; }\
    _Pragma("unroll")                                                            \
    for (int _j = 0; _j < 16; ++_j) if (_j == _mj) sL[_j] = (sv);                \
    _Pragma("unroll")                                                            \
    for (int _j = 0; _j < 8; ++_j) if (_j == (_mj >> 1))                         \
        pL[_j] = (_mj & 1) ? ((pL[_j] & 0x0000FFFFu) | ((uint32_t)(kv) << 16))   \
                           : ((pL[_j] & 0xFFFF0000u) | (uint32_t)(kv));          \
    _mn = sL[0];                                                                 \
    _Pragma("unroll")                                                            \
    for (int _j = 1; _j < 16; ++_j) _mn = fminf(_mn, sL[_j]);                    \
    thrL = _mn;                                                                  \
}

__global__ void __launch_bounds__(256) convert_k_kernel(const float* __restrict__ K) {
    size_t i = ((size_t)blockIdx.x*256u + threadIdx.x) * 8u;
    float4 a = *reinterpret_cast<const float4*>(K+i);
    float4 b = *reinterpret_cast<const float4*>(K+i+4);
    __nv_bfloat162* o = reinterpret_cast<__nv_bfloat162*>(g_kbf+i);
    o[0] = __floats2bfloat162_rn(a.x,a.y);
    o[1] = __floats2bfloat162_rn(a.z,a.w);
    o[2] = __floats2bfloat162_rn(b.x,b.y);
    o[3] = __floats2bfloat162_rn(b.z,b.w);
}

__global__ __launch_bounds__(256, 2)
void praxis_mma_kernel(const float* __restrict__ Q,
                       const float* __restrict__ Outp,
                       const float* __restrict__ Gate,
                       const float* __restrict__ Kmem,
                       const float* __restrict__ Vmem,
                       float* __restrict__ Out)
{
    extern __shared__ char smem[];
    float*    QSf = reinterpret_cast<float*>(smem);           // [d][q] fp32
    uint16_t* CIp = reinterpret_cast<uint16_t*>(smem + SM_CI);
    float*    CSp = reinterpret_cast<float*>(smem + SM_CS);
    float*    FSp = reinterpret_cast<float*>(smem + SM_FS);
    int*      FIp = reinterpret_cast<int*>(smem + SM_FI);

    const int tid  = threadIdx.x;
    const int wid  = tid >> 5;
    const int lane = tid & 31;
    const int h    = blockIdx.y;
    const int q0   = blockIdx.x * TQ;

    const float* KH = Kmem + (size_t)h * Mc * Dc;
    const __nv_bfloat16* KB = g_kbf + (size_t)h * Mc * Dc;

    // ---- verbatim qn loader (EXACT R2 arithmetic; reused for rescore) ----
    #define LOAD_QN()                                                            \
    {   _Pragma("unroll")                                                        \
        for (int half = 0; half < 2; ++half) {                                   \
            const int q    = tid >> 2;                                           \
            const int part = tid & 3;                                            \
            const int qrow = half * 64 + q;                                      \
            const int qg   = q0 + qrow;                                          \
            const int bq   = qg >> 11;                                           \
            const int sq   = qg & 2047;                                          \
            const float* qp = Q + ((((size_t)bq*Hc + h)*Sc + sq)*Dc) + part*32;  \
            float4 v[8]; float ss = 0.f;                                         \
            _Pragma("unroll")                                                    \
            for (int r = 0; r < 8; ++r) {                                        \
                v[r] = reinterpret_cast<const float4*>(qp)[r];                   \
                ss += v[r].x*v[r].x + v[r].y*v[r].y + v[r].z*v[r].z + v[r].w*v[r].w; \
            }                                                                    \
            ss += __shfl_xor_sync(FULLMASK, ss, 1);                              \
            ss += __shfl_xor_sync(FULLMASK, ss, 2);                              \
            const float inv = 1.0f / fmaxf(sqrtf(ss), 1e-12f);                   \
            _Pragma("unroll")                                                    \
            for (int r = 0; r < 8; ++r) {                                        \
                const int d = part*32 + r*4;                                     \
                QSf[(d+0)*TQ + qrow] = v[r].x * inv;                             \
                QSf[(d+1)*TQ + qrow] = v[r].y * inv;                             \
                QSf[(d+2)*TQ + qrow] = v[r].z * inv;                             \
                QSf[(d+3)*TQ + qrow] = v[r].w * inv;                             \
            }                                                                    \
        }                                                                        \
    }

    LOAD_QN();
    __syncthreads();

    // ---- build A fragments: warp w owns query rows 16w..16w+15 ----
    const int g  = lane >> 2;          // 0..7
    const int t4 = lane & 3;           // 0..3
    uint32_t afr[8][4];
    {
        const int rA = wid*16 + g;
        const int rB = rA + 8;
        #pragma unroll
        for (int ks = 0; ks < 8; ++ks) {
            const int k0 = t4*2 + ks*16;
            afr[ks][0] = packbf(QSf[(k0+0)*TQ + rA], QSf[(k0+1)*TQ + rA]);
            afr[ks][1] = packbf(QSf[(k0+0)*TQ + rB], QSf[(k0+1)*TQ + rB]);
            afr[ks][2] = packbf(QSf[(k0+8)*TQ + rA], QSf[(k0+9)*TQ + rA]);
            afr[ks][3] = packbf(QSf[(k0+8)*TQ + rB], QSf[(k0+9)*TQ + rB]);
        }
    }
    __syncthreads();   // QS reads done; region becomes K staging buffers

    // ---- K staging: tile t -> buffer b (1024 x 16B chunks, 4 per thread) ----
    const uint32_t kb_u32 = (uint32_t)__cvta_generic_to_shared(smem + SM_KB);
    #define LOADTILE(t, b)                                                       \
    {   _Pragma("unroll")                                                        \
        for (int _i = 0; _i < 4; ++_i) {                                         \
            const int _c = tid + 256*_i;                                         \
            const int _row = _c >> 4, _seg = _c & 15;                            \
            cpasync16(kb_u32 + (uint32_t)((b)*TBYTES + _row*KSTRB + _seg*16),    \
                      reinterpret_cast<const char*>(KB)                          \
                      + ((size_t)((t)*TILEK + _row))*256 + _seg*16);             \
        }                                                                        \
    }

    LOADTILE(0, 0) CP_COMMIT();
    LOADTILE(1, 1) CP_COMMIT();

    // ---- per-lane candidate lists: top-16 per (row, column-stream) ----
    float sA[16], sB[16]; uint32_t pA[8], pB[8];
    #pragma unroll
    for (int j = 0; j < 16; ++j) { sA[j] = -1e30f; sB[j] = -1e30f; }
    #pragma unroll
    for (int j = 0; j < 8; ++j) { pA[j] = 0xFFFFFFFFu; pB[j] = 0xFFFFFFFFu; }
    float thrA = -1e30f, thrB = -1e30f;

    // ---- main loop over 512 key tiles ----
    #pragma unroll 1
    for (int t = 0; t < NT; ++t) {
        CP_WAIT1();
        __syncthreads();
        const char* kbuf = smem + SM_KB + (t % 3) * TBYTES;

        #pragma unroll 1
        for (int blk = 0; blk < 8; ++blk) {
            const char* bp = kbuf + (blk*8 + g)*KSTRB + t4*4;
            float c0 = 0.f, c1 = 0.f, c2 = 0.f, c3 = 0.f;
            #pragma unroll
            for (int ks = 0; ks < 8; ++ks) {
                const uint32_t b0 = *reinterpret_cast<const uint32_t*>(bp + ks*32);
                const uint32_t b1 = *reinterpret_cast<const uint32_t*>(bp + ks*32 + 16);
                mma16816(c0, c1, c2, c3,
                         afr[ks][0], afr[ks][1], afr[ks][2], afr[ks][3], b0, b1);
            }
            // filter: rows rA (c0,c1 = keys kb,kb+1) and rB (c2,c3)
            const int kb = t*TILEK + blk*8 + t4*2;
            if (fmaxf(c0, c1) > thrA) {
                if (c0 > thrA) { INSERT(sA, pA, thrA, c0, kb) }
                if (c1 > thrA) { INSERT(sA, pA, thrA, c1, kb + 1) }
            }
            if (fmaxf(c2, c3) > thrB) {
                if (c2 > thrB) { INSERT(sB, pB, thrB, c2, kb) }
                if (c3 > thrB) { INSERT(sB, pB, thrB, c3, kb + 1) }
            }
        }

        if (t + 2 < NT) { LOADTILE(t + 2, (t + 2) % 3) }
        CP_COMMIT();
    }
    CP_WAIT0();
    __syncthreads();

    // ---- dump candidate indices (u16) ----
    {
        const int rA = wid*16 + g;
        const int rB = rA + 8;
        #pragma unroll
        for (int j = 0; j < 16; ++j) {
            CIp[rA*64 + t4*16 + j] = (uint16_t)((pA[j >> 1] >> ((j & 1) * 16)) & 0xFFFFu);
            CIp[rB*64 + t4*16 + j] = (uint16_t)((pB[j >> 1] >> ((j & 1) * 16)) & 0xFFFFu);
        }
    }
    __syncthreads();

    // ---- rebuild fp32 qn (verbatim) and rescore 64 candidates per row ----
    LOAD_QN();
    __syncthreads();
    {
        const int row  = tid >> 1;
        const int half = tid & 1;
        #pragma unroll 1
        for (int j = 0; j < 32; ++j) {
            const int idx = (int)CIp[row*64 + half*32 + j];
            const float4* kp = reinterpret_cast<const float4*>(KH + (size_t)idx * Dc);
            float s = 0.f;
            #pragma unroll
            for (int m = 0; m < 32; ++m) {
                const float4 kv = kp[m];
                s = fmaf(QSf[(4*m+0)*TQ + row], kv.x, s);
                s = fmaf(QSf[(4*m+1)*TQ + row], kv.y, s);
                s = fmaf(QSf[(4*m+2)*TQ + row], kv.z, s);
                s = fmaf(QSf[(4*m+3)*TQ + row], kv.w, s);
            }
            CSp[row*64 + half*32 + j] = s;
        }
    }
    __syncthreads();

    // ---- select top-16 of 64, tie rule (score desc, index asc) ----
    if (tid < 128) {
        #pragma unroll 1
        for (int n = 0; n < 16; ++n) {
            float bs = -1e30f; int bi = 0x7fffffff; int bj = 0;
            #pragma unroll 1
            for (int j = 0; j < 64; ++j) {
                const float v = CSp[tid*64 + j];
                const int  vi = (int)CIp[tid*64 + j];
                if (v > bs || (v == bs && vi < bi)) { bs = v; bi = vi; bj = j; }
            }
            FSp[tid*16 + n] = bs;
            FIp[tid*16 + n] = bi;
            CSp[tid*64 + bj] = -1e30f;
        }
    }
    __syncthreads();

    // ---- epilogue: gather V, weighted sum, gate blend (verbatim) ----
    const float gv = Gate[h];
    const float gg = 1.0f / (1.0f + expf(-gv));
    const float og = 1.0f - gg;
    const float* VH = Vmem + (size_t)h * Mc * Dc;

    const int r    = tid >> 1;
    const int part = tid & 1;

    float4 a[16];
    #pragma unroll
    for (int m = 0; m < 16; ++m) a[m] = make_float4(0.f, 0.f, 0.f, 0.f);

    #pragma unroll 1
    for (int j = 0; j < 16; ++j) {
        const float sj = FSp[r*16 + j];
        const int   vj = FIp[r*16 + j];
        const float4* vp = reinterpret_cast<const float4*>(VH + (size_t)vj * Dc + part * 64);
        #pragma unroll
        for (int m = 0; m < 16; ++m) {
            const float4 v = vp[m];
            a[m].x += sj * v.x; a[m].y += sj * v.y;
            a[m].z += sj * v.z; a[m].w += sj * v.w;
        }
    }
    {
        const int qg = q0 + r;
        const int bq = qg >> 11;
        const int sq = qg & 2047;
        const size_t off = (((size_t)bq * Hc + h) * Sc + sq) * Dc + part * 64;
        #pragma unroll
        for (int m = 0; m < 16; ++m) {
            const float4 o = *reinterpret_cast<const float4*>(Outp + off + 4*m);
            float4 rr;
            rr.x = gg * a[m].x + og * o.x;
            rr.y = gg * a[m].y + og * o.y;
            rr.z = gg * a[m].z + og * o.z;
            rr.w = gg * a[m].w + og * o.w;
            *reinterpret_cast<float4*>(Out + off + 4*m) = rr;
        }
    }
}

extern "C" void kernel_launch(void* const* d_in, const int* in_sizes, int n_in,
                              void* d_out, int out_size) {
    // metadata order: inputs(0), query(1), key(2), value(3), outputs(4),
    //                 gate(5), key_memories(6), value_memories(7)
    const float* query   = (const float*)d_in[1];
    const float* outputs = (const float*)d_in[4];
    const float* gate    = (const float*)d_in[5];
    const float* kmem    = (const float*)d_in[6];
    const float* vmem    = (const float*)d_in[7];
    float* out = (float*)d_out;

    const int nconv = (Hc * Mc * Dc) / (256 * 8);   // 16384 blocks
    convert_k_kernel<<<nconv, 256>>>(kmem);

    cudaFuncSetAttribute(praxis_mma_kernel,
                         cudaFuncAttributeMaxDynamicSharedMemorySize, SM_TOTAL);
    dim3 grid(NQ / TQ, Hc);   // 32 x 8 = 256 CTAs
    praxis_mma_kernel<<<grid, 256, SM_TOTAL>>>(query, outputs, gate, kmem, vmem, out);
}